// round 1
// baseline (speedup 1.0000x reference)
#include <cuda_runtime.h>

#define PI_F 3.14159265358979323846f
#define PI_D 3.14159265358979323846

#define LDIM 512
#define ADIM 181
#define PDIM 1024
#define BDIM 2

#define CH   46      // angle rows staged per chunk in backprojection
#define RSTR 520     // smem row stride (floats): [3]=0 guard, data [4..515], [516]=0 guard

// ---------------- device scratch (no allocation allowed) ----------------
__device__ float  g_cos[PDIM];                 // cos(2*pi*q/1024)
__device__ float  g_F[PDIM];                   // frequency filter (ramp * shifted hann)
__device__ float  g_hr[PDIM];                  // real(ifft(F))  -- time-domain taps
__device__ float2 g_trig[ADIM];                // (cos th, sin th), th = angle + pi/2
__device__ float  g_sino_f[BDIM * ADIM * LDIM];// filtered sinogram

// ---------------- setup: cos table + per-angle trig ----------------
__global__ void k_init(const float* __restrict__ angles, int A) {
    int t = threadIdx.x;
    if (t < PDIM) g_cos[t] = (float)cospi((double)t / 512.0); // cos(2*pi*t/1024)
    if (t < A && t < ADIM) {
        float th = angles[t] + (float)(PI_D * 0.5);
        g_trig[t] = make_float2(cosf(th), sinf(th));
    }
}

// ---------------- F[k] = ramp[k] * fftshift(hanning(P))[k] ----------------
// ramp[k] = 2*Re(fft(f))[k] = 0.5 + 4 * sum_{odd m<=511} f[m] cos(2*pi*k*m/P)
// using f[m] = -1/(pi*m)^2 (odd m), f symmetric f[m]=f[P-m].
__global__ void k_ramp(void) {
    __shared__ float sred[4];
    int k = blockIdx.x;
    int t = threadIdx.x; // 128 threads
    float sum = 0.f;
    for (int j = t; j < 256; j += 128) {
        int m = 2 * j + 1;
        float fm = -1.0f / (PI_F * PI_F * (float)m * (float)m);
        sum = fmaf(fm, g_cos[(k * m) & (PDIM - 1)], sum);
    }
    #pragma unroll
    for (int o = 16; o; o >>= 1) sum += __shfl_down_sync(0xffffffffu, sum, o);
    if ((t & 31) == 0) sred[t >> 5] = sum;
    __syncthreads();
    if (t == 0) {
        float total = sred[0] + sred[1] + sred[2] + sred[3];
        float ramp = 0.5f + 4.0f * total;
        int i = (k + PDIM / 2) & (PDIM - 1);                 // fftshift index
        float w = 0.5f - 0.5f * (float)cospi(2.0 * (double)i / 1023.0); // np.hanning(1024)
        g_F[k] = ramp * w;
    }
}

// ---------------- hr[n] = (1/P) * sum_k F[k] cos(2*pi*k*n/P) ----------------
__global__ void k_hr(void) {
    __shared__ float sred[8];
    int n = blockIdx.x;
    int t = threadIdx.x; // 256 threads
    float sum = 0.f;
    for (int k = t; k < PDIM; k += 256)
        sum = fmaf(g_F[k], g_cos[(k * n) & (PDIM - 1)], sum);
    #pragma unroll
    for (int o = 16; o; o >>= 1) sum += __shfl_down_sync(0xffffffffu, sum, o);
    if ((t & 31) == 0) sred[t >> 5] = sum;
    __syncthreads();
    if (t == 0) {
        float total = 0.f;
        #pragma unroll
        for (int w = 0; w < 8; w++) total += sred[w];
        g_hr[n] = total * (1.0f / (float)PDIM);
    }
}

// ---------------- filtering: y[n] = sum_{m=0}^{511} x[m] * hr[(n-m) mod 1024] ----------------
// hr duplicated into 1536 smem entries so (n-m) mod P becomes plain offset n+1024-m.
__global__ void k_filter(const float* __restrict__ sino) {
    __shared__ float xs[LDIM];
    __shared__ float hsx[1536];
    int row = blockIdx.x;
    int t = threadIdx.x; // 256
    const float* x = sino + row * LDIM;
    xs[t] = x[t];
    xs[t + 256] = x[t + 256];
    for (int q = t; q < 1536; q += 256) hsx[q] = g_hr[q & (PDIM - 1)];
    __syncthreads();
    const float* h0 = hsx + t + 1024;
    const float* h1 = hsx + t + 256 + 1024;
    float a0 = 0.f, a1 = 0.f;
    #pragma unroll 8
    for (int m = 0; m < LDIM; m++) {
        float xv = xs[m];
        a0 = fmaf(xv, h0[-m], a0);
        a1 = fmaf(xv, h1[-m], a1);
    }
    g_sino_f[row * LDIM + t] = a0;
    g_sino_f[row * LDIM + t + 256] = a1;
}

// ---------------- backprojection ----------------
// block = (32,8) threads; tile = 32 (j, lanes) x 64 (i, 8 per thread).
// Stages CH angle rows (zero-guard padded) in dynamic smem; circle==1 path is branch-free.
__global__ void __launch_bounds__(256) k_bp(
    float* __restrict__ out, const int* __restrict__ circ, int A, int B)
{
    extern __shared__ float sm[];
    float*  srows = sm;
    float2* strig = (float2*)(sm + CH * RSTR);

    const int tx = threadIdx.x, ty = threadIdx.y;
    const int tid = ty * 32 + tx;
    const int b  = blockIdx.z;
    const int j  = blockIdx.x * 32 + tx;
    const int i0 = blockIdx.y * 64 + ty;
    const int circle = circ[0];

    for (int a = tid; a < A; a += 256) strig[a] = g_trig[a];

    const int dj = j - LDIM / 2;
    const float djf = (float)dj;
    float acc[8];
    float fdi[8];
    unsigned maskbits = 0;
    #pragma unroll
    for (int k = 0; k < 8; k++) {
        acc[k] = 0.f;
        int di = i0 + 8 * k - LDIM / 2;
        bool outside = (di * di + dj * dj) > (LDIM / 2) * (LDIM / 2);
        if (outside) maskbits |= (1u << k);
        // masked pixels get a safe sampling coordinate when circle is on (output forced to 0)
        fdi[k] = (circle && outside) ? 0.0f : (float)di;
    }

    const float* src = g_sino_f + b * A * LDIM;

    for (int a0 = 0; a0 < A; a0 += CH) {
        int ch = min(CH, A - a0);
        __syncthreads();
        // cooperative copy of ch filtered rows into padded smem rows
        int nf4 = ch * (LDIM / 4);
        for (int q = tid; q < nf4; q += 256) {
            int r = q >> 7;
            int c = q & 127;
            float4 v = ((const float4*)(src + (a0 + r) * LDIM))[c];
            *((float4*)(srows + r * RSTR + 4 + 4 * c)) = v;
        }
        for (int r = tid; r < ch; r += 256) {
            srows[r * RSTR + 3] = 0.f;          // left zero guard  (i0 == -1)
            srows[r * RSTR + 4 + LDIM] = 0.f;   // right zero guard (i1 == 512)
        }
        __syncthreads();

        if (circle) {
            // inside circle: |t| <= 256 -> u in [3.5, 515.5] after folding +4 offset: no bounds checks
            for (int r = 0; r < ch; r++) {
                float2 cs = strig[a0 + r];
                float base = fmaf(djf, cs.y, 255.5f + 4.0f);
                const float* rp = srows + r * RSTR;
                #pragma unroll
                for (int k = 0; k < 8; k++) {
                    float u = fmaf(fdi[k], cs.x, base);
                    float fl = floorf(u);
                    float frac = u - fl;
                    int idx = (int)fl;
                    float g0 = rp[idx];
                    float g1 = rp[idx + 1];
                    acc[k] = fmaf(1.0f - frac, g0, fmaf(frac, g1, acc[k]));
                }
            }
        } else {
            // generic path (never used by the dataset inputs, kept for correctness)
            for (int r = 0; r < ch; r++) {
                float2 cs = strig[a0 + r];
                float base = fmaf(djf, cs.y, 255.5f);
                const float* rp = srows + r * RSTR + 4;
                #pragma unroll
                for (int k = 0; k < 8; k++) {
                    float u = fmaf(fdi[k], cs.x, base);
                    float fl = floorf(u);
                    float frac = u - fl;
                    int ii0 = (int)fl;
                    int ii1 = ii0 + 1;
                    float w0 = (ii0 >= 0 && ii0 < LDIM) ? (1.0f - frac) : 0.0f;
                    float w1 = (ii1 >= 0 && ii1 < LDIM) ? frac : 0.0f;
                    int c0 = min(max(ii0, 0), LDIM - 1);
                    int c1 = min(max(ii1, 0), LDIM - 1);
                    acc[k] = fmaf(w0, rp[c0], fmaf(w1, rp[c1], acc[k]));
                }
            }
        }
    }

    #pragma unroll
    for (int k = 0; k < 8; k++) {
        int ii = i0 + 8 * k;
        float v = (circle && ((maskbits >> k) & 1u)) ? 0.0f : acc[k];
        out[((size_t)b * LDIM + ii) * LDIM + j] = v;
    }
}

// ---------------- launch ----------------
extern "C" void kernel_launch(void* const* d_in, const int* in_sizes, int n_in,
                              void* d_out, int out_size) {
    // robust input identification by size: sino is the big one, circle is size 1, angles is the rest
    int si = 0, ai = 1, ci = 2;
    for (int i = 0; i < n_in; i++) {
        if (in_sizes[i] > in_sizes[si]) si = i;
    }
    for (int i = 0; i < n_in; i++) {
        if (i == si) continue;
        if (in_sizes[i] == 1) ci = i; else ai = i;
    }
    const float* sino   = (const float*)d_in[si];
    const float* angles = (const float*)d_in[ai];
    const int*   circ   = (const int*)d_in[ci];

    int A = in_sizes[ai];
    if (A > ADIM) A = ADIM;
    int BL = in_sizes[si] / A;     // B * L
    int B  = BL / LDIM;            // batch
    if (B < 1) B = 1;
    if (B > BDIM) B = BDIM;
    int nrows = B * A;

    k_init<<<1, 1024>>>(angles, A);
    k_ramp<<<PDIM, 128>>>();
    k_hr<<<PDIM, 256>>>();
    k_filter<<<nrows, 256>>>(sino);

    size_t smem = (size_t)(CH * RSTR + 2 * ADIM + 2) * sizeof(float);
    cudaFuncSetAttribute(k_bp, cudaFuncAttributeMaxDynamicSharedMemorySize, (int)smem);
    dim3 grid(LDIM / 32, LDIM / 64, B);
    dim3 blk(32, 8);
    k_bp<<<grid, blk, smem>>>((float*)d_out, circ, A, B);
}

// round 2
// speedup vs baseline: 1.6635x; 1.6635x over previous
#include <cuda_runtime.h>
#include <stdint.h>

#define PI_F 3.14159265358979323846f

#define LDIM 512
#define ADIM 181
#define PDIM 1024
#define BDIM 2

#define CH   23      // angle rows per staging buffer (double-buffered)
#define RSTR 520     // smem row stride (floats): [3]=0 guard, data [4..515], [516]=0 guard
#define BUFSZ (CH * RSTR)

// ---------------- device scratch (no allocation allowed) ----------------
__device__ float  g_F[PDIM];                   // frequency filter (ramp * shifted hann)
__device__ float  g_hr[PDIM];                  // real(ifft(F))  -- time-domain taps
__device__ float2 g_trig[ADIM];                // (cos th, sin th), th = angle + pi/2
__device__ float  g_sino_f[BDIM * ADIM * LDIM];// filtered sinogram

// ---------------- cp.async helpers ----------------
__device__ __forceinline__ uint32_t smem_u32(const void* p) {
    uint32_t a;
    asm("{ .reg .u64 t; cvta.to.shared.u64 t, %1; cvt.u32.u64 %0, t; }" : "=r"(a) : "l"(p));
    return a;
}
__device__ __forceinline__ void cpa16(uint32_t saddr, const void* g) {
    asm volatile("cp.async.cg.shared.global [%0], [%1], 16;" :: "r"(saddr), "l"(g));
}
__device__ __forceinline__ void cpa_commit() {
    asm volatile("cp.async.commit_group;" ::: "memory");
}
__device__ __forceinline__ void cpa_wait0() {
    asm volatile("cp.async.wait_group 0;" ::: "memory");
}
__device__ __forceinline__ void cpa_wait1() {
    asm volatile("cp.async.wait_group 1;" ::: "memory");
}

// ---------------- F[k] = ramp[k] * fftshift(hanning(P))[k]  (+ trig in block 0) ----------------
// ramp[k] = 0.5 + 4 * sum_{odd m<=511} (-1/(pi m)^2) cos(2*pi*k*m/P)
__global__ void k_ramp(const float* __restrict__ angles, int A) {
    __shared__ float sred[4];
    int k = blockIdx.x;
    int t = threadIdx.x; // 128 threads
    float sum = 0.f;
    for (int j = t; j < 256; j += 128) {
        int m = 2 * j + 1;
        float fm = -1.0f / (PI_F * PI_F * (float)m * (float)m);
        int ph = (k * m) & (PDIM - 1);
        sum = fmaf(fm, cospif((float)ph * (1.0f / 512.0f)), sum);
    }
    #pragma unroll
    for (int o = 16; o; o >>= 1) sum += __shfl_down_sync(0xffffffffu, sum, o);
    if ((t & 31) == 0) sred[t >> 5] = sum;
    __syncthreads();
    if (t == 0) {
        float total = sred[0] + sred[1] + sred[2] + sred[3];
        float ramp = 0.5f + 4.0f * total;
        int i = (k + PDIM / 2) & (PDIM - 1);                     // fftshift index
        float w = 0.5f - 0.5f * cospif(2.0f * (float)i / 1023.0f); // np.hanning(1024)
        g_F[k] = ramp * w;
    }
    if (blockIdx.x == 0) {
        for (int a = t; a < A && a < ADIM; a += 128) {
            float th = angles[a] + PI_F * 0.5f;
            float s, c;
            sincosf(th, &s, &c);
            g_trig[a] = make_float2(c, s);
        }
    }
}

// ---------------- hr[n] = (1/P) * sum_k F[k] cos(2*pi*k*n/P) ----------------
__global__ void k_hr(void) {
    __shared__ float sred[8];
    int n = blockIdx.x;
    int t = threadIdx.x; // 256 threads
    float sum = 0.f;
    for (int k = t; k < PDIM; k += 256) {
        int ph = (k * n) & (PDIM - 1);
        sum = fmaf(g_F[k], cospif((float)ph * (1.0f / 512.0f)), sum);
    }
    #pragma unroll
    for (int o = 16; o; o >>= 1) sum += __shfl_down_sync(0xffffffffu, sum, o);
    if ((t & 31) == 0) sred[t >> 5] = sum;
    __syncthreads();
    if (t == 0) {
        float total = 0.f;
        #pragma unroll
        for (int w = 0; w < 8; w++) total += sred[w];
        g_hr[n] = total * (1.0f / (float)PDIM);
    }
}

// ---------------- filtering: y[n] = sum_{m=0}^{511} x[m] * hr[(n-m) mod 1024] ----------------
// 128 threads, 4 consecutive outputs per thread, float4 sliding window over taps.
__global__ void __launch_bounds__(128) k_filter(const float* __restrict__ sino) {
    __shared__ float xs[LDIM];
    __shared__ float hsx[1536];
    int row = blockIdx.x;
    int t = threadIdx.x; // 128
    const float4* x4 = (const float4*)(sino + row * LDIM);
    ((float4*)xs)[t] = x4[t];                    // 128 * float4 = 512 floats
    #pragma unroll
    for (int q = t; q < 384; q += 128)           // hsx[i] = hr[i mod 1024]
        ((float4*)hsx)[q] = ((const float4*)g_hr)[q & 255];
    __syncthreads();

    const int qb = 1024 + 4 * t;                 // window anchor
    float4 Av = *(const float4*)(hsx + qb - 4);  // W[0..3] for m0=0
    float4 Bv = *(const float4*)(hsx + qb);      // W[4..7]
    float acc0 = 0.f, acc1 = 0.f, acc2 = 0.f, acc3 = 0.f;

    #pragma unroll 4
    for (int m0 = 0; m0 < LDIM; m0 += 4) {
        float4 xv = *(const float4*)(xs + m0);   // broadcast
        float w0 = Av.x, w1 = Av.y, w2 = Av.z, w3 = Av.w;
        float w4 = Bv.x, w5 = Bv.y, w6 = Bv.z, w7 = Bv.w;
        acc0 = fmaf(xv.x, w4, fmaf(xv.y, w3, fmaf(xv.z, w2, fmaf(xv.w, w1, acc0))));
        acc1 = fmaf(xv.x, w5, fmaf(xv.y, w4, fmaf(xv.z, w3, fmaf(xv.w, w2, acc1))));
        acc2 = fmaf(xv.x, w6, fmaf(xv.y, w5, fmaf(xv.z, w4, fmaf(xv.w, w3, acc2))));
        acc3 = fmaf(xv.x, w7, fmaf(xv.y, w6, fmaf(xv.z, w5, fmaf(xv.w, w4, acc3))));
        Bv = Av;                                 // shift window down by 4
        Av = *(const float4*)(hsx + qb - m0 - 8);
    }
    float4 outv = make_float4(acc0, acc1, acc2, acc3);
    *((float4*)(g_sino_f + row * LDIM + 4 * t)) = outv;
}

// ---------------- backprojection ----------------
// block = (32,8); tile = 32 (j) x 64 (i, 8 per thread). Double-buffered cp.async staging.
__global__ void __launch_bounds__(256) k_bp(
    float* __restrict__ out, const int* __restrict__ circ, int A, int B)
{
    extern __shared__ float sm[];
    float2* strig = (float2*)(sm + 2 * BUFSZ);

    const int tx = threadIdx.x, ty = threadIdx.y;
    const int tid = ty * 32 + tx;
    const int b  = blockIdx.z;
    const int j  = blockIdx.x * 32 + tx;
    const int i0 = blockIdx.y * 64 + ty;
    const int circle = circ[0];

    // zero guards for both buffers (never overwritten by cp.async)
    for (int rr = tid; rr < 2 * CH; rr += 256) {
        sm[rr * RSTR + 3] = 0.f;
        sm[rr * RSTR + 4 + LDIM] = 0.f;
    }
    for (int a = tid; a < A; a += 256) strig[a] = g_trig[a];

    const int dj = j - LDIM / 2;
    const float djf = (float)dj;
    float accA[8], accB[8];
    float fdi[8];
    unsigned maskbits = 0;
    #pragma unroll
    for (int k = 0; k < 8; k++) {
        accA[k] = 0.f; accB[k] = 0.f;
        int di = i0 + 8 * k - LDIM / 2;
        bool outside = (di * di + dj * dj) > (LDIM / 2) * (LDIM / 2);
        if (outside) maskbits |= (1u << k);
        fdi[k] = (circle && outside) ? 0.0f : (float)di;
    }

    const float* src = g_sino_f + b * A * LDIM;
    const uint32_t sb = smem_u32(sm);
    const int nch = (A + CH - 1) / CH;

    // prefetch chunk 0 into buffer 0
    {
        int ch0 = min(CH, A);
        int n4 = ch0 * (LDIM / 4);
        for (int q = tid; q < n4; q += 256) {
            int r = q >> 7, c = q & 127;
            cpa16(sb + (uint32_t)((r * RSTR + 4 + 4 * c) << 2),
                  src + (size_t)r * LDIM + 4 * c);
        }
        cpa_commit();
    }

    for (int cidx = 0; cidx < nch; cidx++) {
        int a0 = cidx * CH;
        int ch = min(CH, A - a0);
        int buf = cidx & 1;
        if (cidx + 1 < nch) {
            int a1 = a0 + CH;
            int ch1 = min(CH, A - a1);
            int nbuf = (cidx + 1) & 1;
            int n4 = ch1 * (LDIM / 4);
            for (int q = tid; q < n4; q += 256) {
                int r = q >> 7, c = q & 127;
                cpa16(sb + (uint32_t)((nbuf * BUFSZ + r * RSTR + 4 + 4 * c) << 2),
                      src + (size_t)(a1 + r) * LDIM + 4 * c);
            }
            cpa_commit();
            cpa_wait1();
        } else {
            cpa_wait0();
        }
        __syncthreads();

        const float* bufp = sm + buf * BUFSZ;
        if (circle) {
            // inside circle: |t| <= 256 -> idx in [3,515]; guards make it branch-free
            for (int r = 0; r < ch; r++) {
                float2 cs = strig[a0 + r];
                float base = fmaf(djf, cs.y, 255.5f + 4.0f);
                const float* rp = bufp + r * RSTR;
                #pragma unroll
                for (int k = 0; k < 8; k++) {
                    float u = fmaf(fdi[k], cs.x, base);
                    int idx = __float2int_rd(u);
                    float f = u - __int2float_rn(idx);
                    float g0 = rp[idx];
                    float g1 = rp[idx + 1];
                    accA[k] += g0;
                    accB[k] = fmaf(f, g1 - g0, accB[k]);
                }
            }
        } else {
            for (int r = 0; r < ch; r++) {
                float2 cs = strig[a0 + r];
                float base = fmaf(djf, cs.y, 255.5f);
                const float* rp = bufp + r * RSTR + 4;
                #pragma unroll
                for (int k = 0; k < 8; k++) {
                    float u = fmaf(fdi[k], cs.x, base);
                    int ii0 = __float2int_rd(u);
                    float f = u - __int2float_rn(ii0);
                    int ii1 = ii0 + 1;
                    float w0 = (ii0 >= 0 && ii0 < LDIM) ? (1.0f - f) : 0.0f;
                    float w1 = (ii1 >= 0 && ii1 < LDIM) ? f : 0.0f;
                    int c0 = min(max(ii0, 0), LDIM - 1);
                    int c1 = min(max(ii1, 0), LDIM - 1);
                    accA[k] = fmaf(w0, rp[c0], fmaf(w1, rp[c1], accA[k]));
                }
            }
        }
        __syncthreads();
    }

    #pragma unroll
    for (int k = 0; k < 8; k++) {
        int ii = i0 + 8 * k;
        float v = (circle && ((maskbits >> k) & 1u)) ? 0.0f : (accA[k] + accB[k]);
        out[((size_t)b * LDIM + ii) * LDIM + j] = v;
    }
}

// ---------------- launch ----------------
extern "C" void kernel_launch(void* const* d_in, const int* in_sizes, int n_in,
                              void* d_out, int out_size) {
    // identify inputs by size: sino is the big one, circle is size 1, angles otherwise
    int si = 0, ai = 1, ci = 2;
    for (int i = 0; i < n_in; i++)
        if (in_sizes[i] > in_sizes[si]) si = i;
    for (int i = 0; i < n_in; i++) {
        if (i == si) continue;
        if (in_sizes[i] == 1) ci = i; else ai = i;
    }
    const float* sino   = (const float*)d_in[si];
    const float* angles = (const float*)d_in[ai];
    const int*   circ   = (const int*)d_in[ci];

    int A = in_sizes[ai];
    if (A > ADIM) A = ADIM;
    int BL = in_sizes[si] / A;
    int B  = BL / LDIM;
    if (B < 1) B = 1;
    if (B > BDIM) B = BDIM;
    int nrows = B * A;

    k_ramp<<<PDIM, 128>>>(angles, A);
    k_hr<<<PDIM, 256>>>();
    k_filter<<<nrows, 128>>>(sino);

    size_t smem = (size_t)(2 * BUFSZ + 2 * ADIM + 2) * sizeof(float);
    cudaFuncSetAttribute(k_bp, cudaFuncAttributeMaxDynamicSharedMemorySize, (int)smem);
    dim3 grid(LDIM / 32, LDIM / 64, B);
    dim3 blk(32, 8);
    k_bp<<<grid, blk, smem>>>((float*)d_out, circ, A, B);
}